// round 7
// baseline (speedup 1.0000x reference)
#include <cuda_runtime.h>
#include <math.h>

#define R 1024
#define B 16
#define D 1024
#define K_ACTIVE 20
#define FB_DECAY 0.9f
#define REFR_W 1.0f
#define FB_W 0.5f

// selected region indices per batch, in selection order
__device__ int d_sel[B * K_ACTIVE];

// ---------------------------------------------------------------------------
// Kernel 1: fused per-(r,b) row reductions + zero-fill of the Hs output row.
//   adj[b,r] = dot(H,w) - theta[r] - refr[b,r] - 0.5*(0.9*fb + 0.1*||msg||)
//   Hs[r,b,:] = 0   (active rows overwritten by the scatter kernel)
// ---------------------------------------------------------------------------
__global__ void __launch_bounds__(256)
score_zero_kernel(const float4* __restrict__ H,
                  const float4* __restrict__ M,
                  const float4* __restrict__ w,
                  const float*  __restrict__ theta,
                  const float*  __restrict__ refr,
                  const float*  __restrict__ fb,
                  float* __restrict__ adj_out,
                  float4* __restrict__ hs_out)
{
    __shared__ float4 s_w[D / 4];
    s_w[threadIdx.x] = w[threadIdx.x];
    __syncthreads();

    int gw   = blockIdx.x * 8 + (threadIdx.x >> 5);   // row id rb
    int lane = threadIdx.x & 31;
    int r = gw >> 4;
    int b = gw & 15;

    const float4* hrow = H + (size_t)gw * (D / 4);
    const float4* mrow = M + (size_t)gw * (D / 4);
    float4*       orow = hs_out + (size_t)gw * (D / 4);
    const float4 z4 = make_float4(0.f, 0.f, 0.f, 0.f);

    float dot = 0.f, ss = 0.f;
#pragma unroll
    for (int i = 0; i < (D / 4) / 32; i++) {
        int j = i * 32 + lane;
        float4 hv = __ldcs(&hrow[j]);
        float4 mv = __ldcs(&mrow[j]);
        float4 wv = s_w[j];
        dot += hv.x * wv.x + hv.y * wv.y + hv.z * wv.z + hv.w * wv.w;
        ss  += mv.x * mv.x + mv.y * mv.y + mv.z * mv.z + mv.w * mv.w;
        __stcs(&orow[j], z4);
    }
#pragma unroll
    for (int o = 16; o > 0; o >>= 1) {
        dot += __shfl_down_sync(0xffffffffu, dot, o);
        ss  += __shfl_down_sync(0xffffffffu, ss,  o);
    }
    if (lane == 0) {
        int br = b * R + r;
        float fb_new = FB_DECAY * fb[br] + (1.0f - FB_DECAY) * sqrtf(ss);
        adj_out[br] = dot - theta[r] - REFR_W * refr[br] - FB_W * fb_new;
    }
}

// ordered-uint transform: max(ord(f)) <=> max(f)
__device__ __forceinline__ unsigned f2ord(float f) {
    unsigned u = __float_as_uint(f);
    return u ^ (((int)u >> 31) | 0x80000000u);
}

__device__ __forceinline__ unsigned long long row_max(
    const unsigned long long* __restrict__ my)
{
    const ulonglong2* m2 = (const ulonglong2*)my;
    unsigned long long a = 0, b = 0;
#pragma unroll
    for (int j = 0; j < 8; j++) {
        ulonglong2 x = m2[2 * j];
        ulonglong2 y = m2[2 * j + 1];
        a = max(a, max(x.x, x.y));
        b = max(b, max(y.x, y.y));
    }
    return max(a, b);
}

// ---------------------------------------------------------------------------
// Kernel 2: per-batch greedy hex NMS (warp 0) + hard write + d_sel record.
// Incremental hierarchical argmax:
//   - lane l owns grid row l (32 contiguous entries), keeps its max in a reg
//   - key = (ord(score) << 32) | ~idx  -> max key == JAX-stable winner
//   - warp reduction = 2x REDUX (__reduce_max_sync)
//   - suppression hits only rows {rr-1, rr, rr+1} -> 3 lanes re-scan
// ---------------------------------------------------------------------------
__global__ void __launch_bounds__(256)
nms_kernel(const float* __restrict__ adj,
           float* __restrict__ hard)
{
    const int b    = blockIdx.x;
    const int t    = threadIdx.x;
    const int lane = t & 31;
    const int warp = t >> 5;

    __shared__ unsigned long long ks[R];
    __shared__ float hm[R];

    for (int i = t; i < R; i += 256) {
        float v = adj[b * R + i];
        ks[i] = ((unsigned long long)f2ord(v) << 32) | (unsigned)(~i);
        hm[i] = 0.f;
    }
    __syncthreads();

    if (warp == 0) {
        const unsigned long long* my = ks + lane * 32;  // lane owns grid row
        unsigned long long best = row_max(my);

        for (int it = 0; it < K_ACTIVE; it++) {
            unsigned hi = (unsigned)(best >> 32);
            unsigned mx = __reduce_max_sync(0xffffffffu, hi);
            unsigned lo = (hi == mx) ? (unsigned)best : 0u;
            lo = __reduce_max_sync(0xffffffffu, lo);
            int s = (int)(~lo) & (R - 1);

            int rr = s >> 5, cc = s & 31;
            if (lane == 0) { d_sel[b * K_ACTIVE + it] = s; hm[s] = 1.f; }
            // lanes 0..6 suppress s and its 6 hex neighbors (32x32 torus)
            if (lane < 7) {
                int tgt;
                switch (lane) {
                    case 0: tgt = s; break;
                    case 1: tgt = (rr << 5) | ((cc - 1) & 31); break;
                    case 2: tgt = (rr << 5) | ((cc + 1) & 31); break;
                    case 3: tgt = (((rr - 1) & 31) << 5) | cc; break;
                    case 4: tgt = (((rr + 1) & 31) << 5) | cc; break;
                    case 5: tgt = (((rr - 1) & 31) << 5) | ((cc + 1) & 31); break;
                    default: tgt = (((rr + 1) & 31) << 5) | ((cc - 1) & 31); break;
                }
                ks[tgt] = 0ull;
            }
            __syncwarp();
            // only the 3 affected rows re-scan
            int dl = (lane - rr) & 31;
            if (dl <= 1 || dl == 31)
                best = row_max(my);
        }
    }
    __syncthreads();

    // hard[b,:]  (1024 floats = 256 float4, one per thread)
    ((float4*)(hard + b * R))[t] = ((const float4*)hm)[t];
}

// ---------------------------------------------------------------------------
// Kernel 3: scatter-copy the 320 active rows: Hs[r,b,:] = H[r,b,:].
// One block per selection, one float4 per thread -> no dependence chains.
// (ste = hard + sigma - stopgrad(sigma): numerically hard, err < 6e-8.)
// ---------------------------------------------------------------------------
__global__ void __launch_bounds__(256)
scatter_kernel(const float4* __restrict__ H,
               float4* __restrict__ out)
{
    int bi   = blockIdx.x;              // 0 .. B*K_ACTIVE-1
    int b    = bi / K_ACTIVE;
    int slot = bi - b * K_ACTIVE;
    int r    = d_sel[b * K_ACTIVE + slot];
    size_t row = (size_t)(r * B + b) * (D / 4);
    out[row + threadIdx.x] = H[row + threadIdx.x];
}

// ---------------------------------------------------------------------------
extern "C" void kernel_launch(void* const* d_in, const int* in_sizes, int n_in,
                              void* d_out, int out_size)
{
    const float* H     = (const float*)d_in[0];   // [R,B,D]
    const float* M     = (const float*)d_in[1];   // [R,B,D]
    const float* w     = (const float*)d_in[2];   // [D]
    const float* theta = (const float*)d_in[3];   // [R]
    const float* refr  = (const float*)d_in[4];   // [B,R]
    const float* fb    = (const float*)d_in[5];   // [B,R]
    // d_in[6] = neighbor_indices: fixed 32x32 toroidal hex grid, computed
    // arithmetically in-kernel.

    float* out  = (float*)d_out;
    float* Hs   = out;                              // [R,B,D]
    float* hard = out + (size_t)R * B * D;          // [B,R]
    float* adj  = hard + (size_t)B * R;             // [B,R]

    score_zero_kernel<<<(R * B) / 8, 256>>>((const float4*)H, (const float4*)M,
                                            (const float4*)w, theta, refr, fb,
                                            adj, (float4*)Hs);
    nms_kernel<<<B, 256>>>(adj, hard);
    scatter_kernel<<<B * K_ACTIVE, 256>>>((const float4*)H, (float4*)Hs);
}